// round 1
// baseline (speedup 1.0000x reference)
#include <cuda_runtime.h>
#include <cstdint>

#define VOC   32768
#define DIM   512
#define BATCH 4096
#define TOPK  64
#define MAXSEL 128

// ---------------- scratch (static device globals; no allocation allowed) ----
__device__ float g_q[(size_t)BATCH * DIM];
__device__ float g_k[(size_t)VOC * DIM];
__device__ float g_v[(size_t)VOC * DIM];
__device__ float g_dots[(size_t)BATCH * VOC];   // 512 MB

// ---------------- helpers ---------------------------------------------------
__device__ __forceinline__ unsigned int f2k(float f) {
    unsigned int u = __float_as_uint(f);
    return (u & 0x80000000u) ? ~u : (u | 0x80000000u);
}
__device__ __forceinline__ float k2f(unsigned int k) {
    unsigned int u = (k & 0x80000000u) ? (k ^ 0x80000000u) : ~k;
    return __uint_as_float(u);
}

// ---------------- SGEMM: C[M,N] = A[M,K] * op(B) (+ bias) -------------------
// TRANSB=false: B is [K,N] row-major.  TRANSB=true: B is [N,K] row-major (C=A*B^T).
// M,N multiples of 128; K multiple of 8.
template <bool TRANSB, bool BIAS>
__global__ __launch_bounds__(256)
void sgemm128(const float* __restrict__ A, const float* __restrict__ B,
              const float* __restrict__ bias, float* __restrict__ C,
              int M, int N, int K)
{
    __shared__ float As[8][128];
    __shared__ float Bs[8][128];

    const int tid = threadIdx.x;
    const int bm = blockIdx.y * 128;
    const int bn = blockIdx.x * 128;

    // A (and transposed-B) load mapping: 128 rows x 8 cols, one float4/thread
    const int a_row = tid >> 1;          // 0..127
    const int a_col = (tid & 1) * 4;     // 0 or 4
    // non-transposed B load mapping: 8 rows x 128 cols, one float4/thread
    const int b_row = tid >> 5;          // 0..7
    const int b_col = (tid & 31) * 4;    // 0..124

    const int tx = tid & 15;             // 16 x 16 thread grid, 8x8 each
    const int ty = tid >> 4;

    float acc[8][8];
#pragma unroll
    for (int i = 0; i < 8; i++)
#pragma unroll
        for (int j = 0; j < 8; j++) acc[i][j] = 0.0f;

    for (int k0 = 0; k0 < K; k0 += 8) {
        // load A tile (transposed into smem)
        float4 av = *reinterpret_cast<const float4*>(
            A + (size_t)(bm + a_row) * K + (k0 + a_col));
        As[a_col + 0][a_row] = av.x;
        As[a_col + 1][a_row] = av.y;
        As[a_col + 2][a_row] = av.z;
        As[a_col + 3][a_row] = av.w;

        if (TRANSB) {
            float4 bv = *reinterpret_cast<const float4*>(
                B + (size_t)(bn + a_row) * K + (k0 + a_col));
            Bs[a_col + 0][a_row] = bv.x;
            Bs[a_col + 1][a_row] = bv.y;
            Bs[a_col + 2][a_row] = bv.z;
            Bs[a_col + 3][a_row] = bv.w;
        } else {
            float4 bv = *reinterpret_cast<const float4*>(
                B + (size_t)(k0 + b_row) * N + (bn + b_col));
            *reinterpret_cast<float4*>(&Bs[b_row][b_col]) = bv;
        }
        __syncthreads();

#pragma unroll
        for (int kk = 0; kk < 8; kk++) {
            float af[8], bf[8];
            float4 t;
            t = *reinterpret_cast<const float4*>(&As[kk][ty * 8]);
            af[0] = t.x; af[1] = t.y; af[2] = t.z; af[3] = t.w;
            t = *reinterpret_cast<const float4*>(&As[kk][ty * 8 + 4]);
            af[4] = t.x; af[5] = t.y; af[6] = t.z; af[7] = t.w;
            t = *reinterpret_cast<const float4*>(&Bs[kk][tx * 8]);
            bf[0] = t.x; bf[1] = t.y; bf[2] = t.z; bf[3] = t.w;
            t = *reinterpret_cast<const float4*>(&Bs[kk][tx * 8 + 4]);
            bf[4] = t.x; bf[5] = t.y; bf[6] = t.z; bf[7] = t.w;
#pragma unroll
            for (int i = 0; i < 8; i++)
#pragma unroll
                for (int j = 0; j < 8; j++)
                    acc[i][j] += af[i] * bf[j];
        }
        __syncthreads();
    }

#pragma unroll
    for (int i = 0; i < 8; i++) {
        const int row = bm + ty * 8 + i;
        const int col = bn + tx * 8;
#pragma unroll
        for (int j = 0; j < 8; j += 4) {
            float4 o;
            o.x = acc[i][j + 0];
            o.y = acc[i][j + 1];
            o.z = acc[i][j + 2];
            o.w = acc[i][j + 3];
            if (BIAS) {
                o.x += bias[col + j + 0];
                o.y += bias[col + j + 1];
                o.z += bias[col + j + 2];
                o.w += bias[col + j + 3];
            }
            *reinterpret_cast<float4*>(C + (size_t)row * N + col + j) = o;
        }
    }
}

// ---------------- per-row top-k threshold + softmax + sparse A@V ------------
// one block of 256 threads per batch row; dots row cached as keys in 128KB smem
__global__ __launch_bounds__(256)
void topk_softmax_gather(const float* __restrict__ dots,
                         const float* __restrict__ v,
                         float* __restrict__ out)
{
    extern __shared__ unsigned int keys[];            // VOC entries = 128KB
    __shared__ unsigned int hist[256];
    __shared__ unsigned int scanbuf[2][256];
    __shared__ unsigned int u_red[256];
    __shared__ float        f_red[256];
    __shared__ int   sel_idx[MAXSEL];
    __shared__ float sel_w[MAXSEL];
    __shared__ unsigned int s_prefix;
    __shared__ int s_r;

    const int tid = threadIdx.x;
    const int row = blockIdx.x;
    const float* drow = dots + (size_t)row * VOC;

    // ---- phase 1: load row, convert to sortable keys, track max ----
    unsigned int kmax = 0;
    for (int i = tid; i < VOC; i += 256) {
        unsigned int k = f2k(drow[i]);
        keys[i] = k;
        kmax = max(kmax, k);
    }
    u_red[tid] = kmax;
    __syncthreads();
#pragma unroll
    for (int s = 128; s > 0; s >>= 1) {
        if (tid < s) u_red[tid] = max(u_red[tid], u_red[tid + s]);
        __syncthreads();
    }
    const float mval = k2f(u_red[0]);

    // ---- phase 2: exact radix-select of rank-TOPK key (4 passes, MSB first) ----
    unsigned int prefix = 0, prefmask = 0;
    int r = TOPK;
    for (int pass = 0; pass < 4; pass++) {
        const int shift = 24 - 8 * pass;
        hist[tid] = 0;
        __syncthreads();
        for (int i = tid; i < VOC; i += 256) {
            unsigned int k = keys[i];
            if ((k & prefmask) == prefix)
                atomicAdd(&hist[(k >> shift) & 255u], 1u);
        }
        __syncthreads();
        // suffix sum: cum[b] = sum_{b' >= b} hist[b']
        scanbuf[0][tid] = hist[tid];
        __syncthreads();
        int src = 0;
        for (int off = 1; off < 256; off <<= 1) {
            unsigned int val = scanbuf[src][tid];
            if (tid + off < 256) val += scanbuf[src][tid + off];
            scanbuf[src ^ 1][tid] = val;
            __syncthreads();
            src ^= 1;
        }
        const unsigned int cumb  = scanbuf[src][tid];
        const unsigned int cumb1 = (tid == 255) ? 0u : scanbuf[src][tid + 1];
        if (cumb >= (unsigned int)r && cumb1 < (unsigned int)r) {
            s_prefix = prefix | ((unsigned int)tid << shift);
            s_r = r - (int)cumb1;
        }
        __syncthreads();
        prefix = s_prefix;
        r = s_r;
        prefmask |= 0xFFu << shift;
        __syncthreads();
    }
    const unsigned int thresh = prefix;  // exact key of the rank-64 value

    // ---- phase 3: deterministic compaction of selected elements ----
    int c = 0;
    for (int i = tid; i < VOC; i += 256)
        if (keys[i] >= thresh) c++;
    scanbuf[0][tid] = (unsigned int)c;
    __syncthreads();
    int src = 0;
    for (int off = 1; off < 256; off <<= 1) {
        unsigned int val = scanbuf[src][tid];
        if (tid >= off) val += scanbuf[src][tid - off];
        scanbuf[src ^ 1][tid] = val;
        __syncthreads();
        src ^= 1;
    }
    int pos = (tid == 0) ? 0 : (int)scanbuf[src][tid - 1];
    const int total = (int)scanbuf[src][255];

    float lsum = 0.0f;
    for (int i = tid; i < VOC; i += 256) {
        unsigned int k = keys[i];
        if (k >= thresh) {
            float w = expf(k2f(k) - mval);
            if (pos < MAXSEL) { sel_idx[pos] = i; sel_w[pos] = w; }
            lsum += w;
            pos++;
        }
    }
    f_red[tid] = lsum;
    __syncthreads();
#pragma unroll
    for (int s = 128; s > 0; s >>= 1) {
        if (tid < s) f_red[tid] += f_red[tid + s];
        __syncthreads();
    }
    const float Z = f_red[0];
    const int count = min(total, MAXSEL);

    // ---- phase 4: out[row] = (1/Z) * sum_s w_s * v[idx_s] ----
    float acc0 = 0.0f, acc1 = 0.0f;
    const int d0 = tid * 2;
    for (int s = 0; s < count; s++) {
        const float w = sel_w[s];
        const float2 vv = *reinterpret_cast<const float2*>(
            v + (size_t)sel_idx[s] * DIM + d0);
        acc0 += w * vv.x;
        acc1 += w * vv.y;
    }
    const float inv = 1.0f / Z;
    float2 o;
    o.x = acc0 * inv;
    o.y = acc1 * inv;
    *reinterpret_cast<float2*>(out + (size_t)row * DIM + d0) = o;
}

// ---------------- launch ----------------------------------------------------
extern "C" void kernel_launch(void* const* d_in, const int* in_sizes, int n_in,
                              void* d_out, int out_size)
{
    const float* x  = (const float*)d_in[0];
    const float* cb = (const float*)d_in[1];
    const float* Wq = (const float*)d_in[2];
    const float* bq = (const float*)d_in[3];
    const float* Wk = (const float*)d_in[4];
    const float* bk = (const float*)d_in[5];
    const float* Wv = (const float*)d_in[6];
    const float* bv = (const float*)d_in[7];
    float* out = (float*)d_out;

    float *q, *k, *v, *dots;
    cudaGetSymbolAddress((void**)&q,    g_q);
    cudaGetSymbolAddress((void**)&k,    g_k);
    cudaGetSymbolAddress((void**)&v,    g_v);
    cudaGetSymbolAddress((void**)&dots, g_dots);

    cudaFuncSetAttribute(topk_softmax_gather,
                         cudaFuncAttributeMaxDynamicSharedMemorySize,
                         VOC * (int)sizeof(unsigned int));

    dim3 blk(256);

    // q = x @ Wq + bq        [4096, 512]
    sgemm128<false, true><<<dim3(DIM / 128, BATCH / 128), blk>>>(
        x, Wq, bq, q, BATCH, DIM, DIM);
    // k = codebook @ Wk + bk [32768, 512]
    sgemm128<false, true><<<dim3(DIM / 128, VOC / 128), blk>>>(
        cb, Wk, bk, k, VOC, DIM, DIM);
    // v = codebook @ Wv + bv [32768, 512]
    sgemm128<false, true><<<dim3(DIM / 128, VOC / 128), blk>>>(
        cb, Wv, bv, v, VOC, DIM, DIM);
    // dots = q @ k^T         [4096, 32768]
    sgemm128<true, false><<<dim3(VOC / 128, BATCH / 128), blk>>>(
        q, k, nullptr, dots, BATCH, VOC, DIM);
    // per-row top-64 threshold + softmax + sparse gather of v
    topk_softmax_gather<<<BATCH, blk, VOC * (int)sizeof(unsigned int)>>>(
        dots, v, out);
}

// round 3
// speedup vs baseline: 1.0584x; 1.0584x over previous
#include <cuda_runtime.h>
#include <cstdint>

#define VOC   32768
#define DIM   512
#define BATCH 4096
#define TOPK  64
#define MAXSEL 128

// dots tile config (mma.sync tf32)
#define MT 256
#define NT 128
#define KC 32
#define KITERS (DIM / KC)        // 16
#define LDP 36                   // padded floats per smem row (KC + 4)
#define A_FLOATS (MT * LDP)      // 9216
#define B_FLOATS (NT * LDP)      // 4608
#define ST_FLOATS (2 * A_FLOATS + 2 * B_FLOATS)   // 27648
#define ST_BYTES  (ST_FLOATS * 4)                 // 110592

// ---------------- scratch (static device globals; no allocation allowed) ----
__device__ float g_q [(size_t)BATCH * DIM];
__device__ float g_k [(size_t)VOC * DIM];
__device__ float g_v [(size_t)VOC * DIM];
__device__ float g_qh[(size_t)BATCH * DIM];
__device__ float g_ql[(size_t)BATCH * DIM];
__device__ float g_kh[(size_t)VOC * DIM];
__device__ float g_kl[(size_t)VOC * DIM];
__device__ float g_dots[(size_t)BATCH * VOC];   // 512 MB

// ---------------- PTX helpers ------------------------------------------------
__device__ __forceinline__ uint32_t smem_u32(const void* p) {
    uint32_t a;
    asm("{ .reg .u64 t; cvta.to.shared.u64 t, %1; cvt.u32.u64 %0, t; }"
        : "=r"(a) : "l"(p));
    return a;
}
#define CP_ASYNC16(dst, src) \
    asm volatile("cp.async.cg.shared.global [%0], [%1], 16;" \
                 :: "r"(dst), "l"(src) : "memory")
#define CP_COMMIT()  asm volatile("cp.async.commit_group;" ::: "memory")

__device__ __forceinline__ void mma_tf32(float& c0, float& c1, float& c2, float& c3,
                                         uint32_t a0, uint32_t a1, uint32_t a2, uint32_t a3,
                                         uint32_t b0, uint32_t b1) {
    asm volatile(
        "mma.sync.aligned.m16n8k8.row.col.f32.tf32.tf32.f32 "
        "{%0,%1,%2,%3}, {%4,%5,%6,%7}, {%8,%9}, {%0,%1,%2,%3};"
        : "+f"(c0), "+f"(c1), "+f"(c2), "+f"(c3)
        : "r"(a0), "r"(a1), "r"(a2), "r"(a3), "r"(b0), "r"(b1));
}

// ---------------- misc helpers ----------------------------------------------
__device__ __forceinline__ unsigned int f2k(float f) {
    unsigned int u = __float_as_uint(f);
    return (u & 0x80000000u) ? ~u : (u | 0x80000000u);
}
__device__ __forceinline__ float k2f(unsigned int k) {
    unsigned int u = (k & 0x80000000u) ? (k ^ 0x80000000u) : ~k;
    return __uint_as_float(u);
}

// ---------------- tf32 split: a = hi + lo (both tf32-representable) ---------
__global__ __launch_bounds__(256)
void split_tf32(const float* __restrict__ in, float* __restrict__ hi,
                float* __restrict__ lo, int n)
{
    int i = blockIdx.x * blockDim.x + threadIdx.x;
    if (i >= n) return;
    float a = in[i];
    uint32_t hb, lb;
    asm("cvt.rna.tf32.f32 %0, %1;" : "=r"(hb) : "f"(a));
    float h = __uint_as_float(hb);
    float l = a - h;
    asm("cvt.rna.tf32.f32 %0, %1;" : "=r"(lb) : "f"(l));
    hi[i] = h;
    lo[i] = __uint_as_float(lb);
}

// ---------------- SGEMM (fp32, FFMA) for q/k/v projections -------------------
template <bool TRANSB, bool BIAS>
__global__ __launch_bounds__(256)
void sgemm128(const float* __restrict__ A, const float* __restrict__ B,
              const float* __restrict__ bias, float* __restrict__ C,
              int M, int N, int K)
{
    __shared__ float As[8][128];
    __shared__ float Bs[8][128];

    const int tid = threadIdx.x;
    const int bm = blockIdx.y * 128;
    const int bn = blockIdx.x * 128;

    const int a_row = tid >> 1;
    const int a_col = (tid & 1) * 4;
    const int b_row = tid >> 5;
    const int b_col = (tid & 31) * 4;

    const int tx = tid & 15;
    const int ty = tid >> 4;

    float acc[8][8];
#pragma unroll
    for (int i = 0; i < 8; i++)
#pragma unroll
        for (int j = 0; j < 8; j++) acc[i][j] = 0.0f;

    for (int k0 = 0; k0 < K; k0 += 8) {
        float4 av = *reinterpret_cast<const float4*>(
            A + (size_t)(bm + a_row) * K + (k0 + a_col));
        As[a_col + 0][a_row] = av.x;
        As[a_col + 1][a_row] = av.y;
        As[a_col + 2][a_row] = av.z;
        As[a_col + 3][a_row] = av.w;

        if (TRANSB) {
            float4 bv = *reinterpret_cast<const float4*>(
                B + (size_t)(bn + a_row) * K + (k0 + a_col));
            Bs[a_col + 0][a_row] = bv.x;
            Bs[a_col + 1][a_row] = bv.y;
            Bs[a_col + 2][a_row] = bv.z;
            Bs[a_col + 3][a_row] = bv.w;
        } else {
            float4 bv = *reinterpret_cast<const float4*>(
                B + (size_t)(k0 + b_row) * N + (bn + b_col));
            *reinterpret_cast<float4*>(&Bs[b_row][b_col]) = bv;
        }
        __syncthreads();

#pragma unroll
        for (int kk = 0; kk < 8; kk++) {
            float af[8], bf[8];
            float4 t;
            t = *reinterpret_cast<const float4*>(&As[kk][ty * 8]);
            af[0] = t.x; af[1] = t.y; af[2] = t.z; af[3] = t.w;
            t = *reinterpret_cast<const float4*>(&As[kk][ty * 8 + 4]);
            af[4] = t.x; af[5] = t.y; af[6] = t.z; af[7] = t.w;
            t = *reinterpret_cast<const float4*>(&Bs[kk][tx * 8]);
            bf[0] = t.x; bf[1] = t.y; bf[2] = t.z; bf[3] = t.w;
            t = *reinterpret_cast<const float4*>(&Bs[kk][tx * 8 + 4]);
            bf[4] = t.x; bf[5] = t.y; bf[6] = t.z; bf[7] = t.w;
#pragma unroll
            for (int i = 0; i < 8; i++)
#pragma unroll
                for (int j = 0; j < 8; j++)
                    acc[i][j] += af[i] * bf[j];
        }
        __syncthreads();
    }

#pragma unroll
    for (int i = 0; i < 8; i++) {
        const int row = bm + ty * 8 + i;
        const int col = bn + tx * 8;
#pragma unroll
        for (int j = 0; j < 8; j += 4) {
            float4 o;
            o.x = acc[i][j + 0];
            o.y = acc[i][j + 1];
            o.z = acc[i][j + 2];
            o.w = acc[i][j + 3];
            if (BIAS) {
                o.x += bias[col + j + 0];
                o.y += bias[col + j + 1];
                o.z += bias[col + j + 2];
                o.w += bias[col + j + 3];
            }
            *reinterpret_cast<float4*>(C + (size_t)row * N + col + j) = o;
        }
    }
}

// ---------------- dots = q @ k^T via mma.sync 3xTF32 ------------------------
// CTA tile 256x128, 8 warps (4m x 2n) of 64x64, KC=32 double-buffered cp.async.
__global__ __launch_bounds__(256)
void dots_mma(const float* __restrict__ Ahi, const float* __restrict__ Alo,
              const float* __restrict__ Bhi, const float* __restrict__ Blo,
              float* __restrict__ C)
{
    extern __shared__ __align__(16) float smem[];
    const uint32_t sb = smem_u32(smem);

    const int tid = threadIdx.x;
    const int lane = tid & 31;
    const int wid = tid >> 5;
    const int warpM = wid >> 1;       // 0..3
    const int warpN = wid & 1;        // 0..1
    const int bm = blockIdx.x * MT;   // m fastest -> q tiles stay L2 resident
    const int bn = blockIdx.y * NT;

    const int r = lane >> 2;          // 0..7
    const int c4 = lane & 3;          // 0..3

    float acc[4][8][4];
#pragma unroll
    for (int mt = 0; mt < 4; mt++)
#pragma unroll
        for (int nt = 0; nt < 8; nt++)
#pragma unroll
            for (int i = 0; i < 4; i++) acc[mt][nt][i] = 0.0f;

    // prefetch K-chunk `it` into stage `s` (24 cp.async16 per thread)
    auto prefetch = [&](int it, int s) {
        const int k0 = it * KC;
        const uint32_t st = sb + (uint32_t)s * ST_BYTES;
        // A: thread tid handles row tid of Ah and Al (8 x 16B each)
        {
            const float* gh = Ahi + (size_t)(bm + tid) * DIM + k0;
            const float* gl = Alo + (size_t)(bm + tid) * DIM + k0;
            const uint32_t dh = st + (uint32_t)tid * (LDP * 4);
            const uint32_t dl = dh + A_FLOATS * 4;
#pragma unroll
            for (int c = 0; c < 8; c++) {
                CP_ASYNC16(dh + c * 16, gh + c * 4);
                CP_ASYNC16(dl + c * 16, gl + c * 4);
            }
        }
        // B: threads 0-127 -> Bh row tid, threads 128-255 -> Bl row tid-128
        {
            const int brow = tid & 127;
            const float* g = ((tid < 128) ? Bhi : Blo) + (size_t)(bn + brow) * DIM + k0;
            const uint32_t d = st + (2 * A_FLOATS + (tid >> 7) * B_FLOATS
                                     + (uint32_t)brow * LDP) * 4;
#pragma unroll
            for (int c = 0; c < 8; c++)
                CP_ASYNC16(d + c * 16, g + c * 4);
        }
        CP_COMMIT();
    };

    prefetch(0, 0);

    // per-thread fragment base offsets (floats)
    int aoff[4], boff[8];
#pragma unroll
    for (int mt = 0; mt < 4; mt++)
        aoff[mt] = (warpM * 64 + mt * 16 + r) * LDP + c4;
#pragma unroll
    for (int nt = 0; nt < 8; nt++)
        boff[nt] = (warpN * 64 + nt * 8 + r) * LDP + c4;

    for (int it = 0; it < KITERS; it++) {
        if (it + 1 < KITERS) {
            prefetch(it + 1, (it + 1) & 1);
            asm volatile("cp.async.wait_group %0;" :: "n"(1));
        } else {
            asm volatile("cp.async.wait_group %0;" :: "n"(0));
        }
        __syncthreads();

        const float* stage = smem + (size_t)(it & 1) * ST_FLOATS;
        const float* Ah = stage;
        const float* Al = stage + A_FLOATS;
        const float* Bh = stage + 2 * A_FLOATS;
        const float* Bl = Bh + B_FLOATS;

#pragma unroll
        for (int ks = 0; ks < 4; ks++) {
            const int kb = ks * 8;
            uint32_t ah[4][4], al[4][4], bh[8][2], bl[8][2];
#pragma unroll
            for (int mt = 0; mt < 4; mt++) {
                const int o = aoff[mt] + kb;
                ah[mt][0] = __float_as_uint(Ah[o]);
                ah[mt][1] = __float_as_uint(Ah[o + 8 * LDP]);
                ah[mt][2] = __float_as_uint(Ah[o + 4]);
                ah[mt][3] = __float_as_uint(Ah[o + 8 * LDP + 4]);
                al[mt][0] = __float_as_uint(Al[o]);
                al[mt][1] = __float_as_uint(Al[o + 8 * LDP]);
                al[mt][2] = __float_as_uint(Al[o + 4]);
                al[mt][3] = __float_as_uint(Al[o + 8 * LDP + 4]);
            }
#pragma unroll
            for (int nt = 0; nt < 8; nt++) {
                const int o = boff[nt] + kb;
                bh[nt][0] = __float_as_uint(Bh[o]);
                bh[nt][1] = __float_as_uint(Bh[o + 4]);
                bl[nt][0] = __float_as_uint(Bl[o]);
                bl[nt][1] = __float_as_uint(Bl[o + 4]);
            }
#pragma unroll
            for (int mt = 0; mt < 4; mt++)
#pragma unroll
                for (int nt = 0; nt < 8; nt++) {
                    float* a = acc[mt][nt];
                    mma_tf32(a[0], a[1], a[2], a[3],
                             ah[mt][0], ah[mt][1], ah[mt][2], ah[mt][3],
                             bh[nt][0], bh[nt][1]);
                    mma_tf32(a[0], a[1], a[2], a[3],
                             al[mt][0], al[mt][1], al[mt][2], al[mt][3],
                             bh[nt][0], bh[nt][1]);
                    mma_tf32(a[0], a[1], a[2], a[3],
                             ah[mt][0], ah[mt][1], ah[mt][2], ah[mt][3],
                             bl[nt][0], bl[nt][1]);
                }
        }
        __syncthreads();
    }

    // epilogue: c0,c1 at (row, 2c4), (row, 2c4+1); c2,c3 at row+8
#pragma unroll
    for (int mt = 0; mt < 4; mt++) {
        const int row = bm + warpM * 64 + mt * 16 + r;
#pragma unroll
        for (int nt = 0; nt < 8; nt++) {
            const int col = bn + warpN * 64 + nt * 8 + 2 * c4;
            float2 v0; v0.x = acc[mt][nt][0]; v0.y = acc[mt][nt][1];
            float2 v1; v1.x = acc[mt][nt][2]; v1.y = acc[mt][nt][3];
            *reinterpret_cast<float2*>(C + (size_t)row * VOC + col) = v0;
            *reinterpret_cast<float2*>(C + (size_t)(row + 8) * VOC + col) = v1;
        }
    }
}

// ---------------- per-row top-k threshold + softmax + sparse A@V ------------
__global__ __launch_bounds__(256)
void topk_softmax_gather(const float* __restrict__ dots,
                         const float* __restrict__ v,
                         float* __restrict__ out)
{
    extern __shared__ unsigned int keys[];            // VOC entries = 128KB
    __shared__ unsigned int hist[256];
    __shared__ unsigned int scanbuf[2][256];
    __shared__ unsigned int u_red[256];
    __shared__ float        f_red[256];
    __shared__ int   sel_idx[MAXSEL];
    __shared__ float sel_w[MAXSEL];
    __shared__ unsigned int s_prefix;
    __shared__ int s_r;

    const int tid = threadIdx.x;
    const int row = blockIdx.x;
    const float* drow = dots + (size_t)row * VOC;

    unsigned int kmax = 0;
    for (int i = tid; i < VOC; i += 256) {
        unsigned int k = f2k(drow[i]);
        keys[i] = k;
        kmax = max(kmax, k);
    }
    u_red[tid] = kmax;
    __syncthreads();
#pragma unroll
    for (int s = 128; s > 0; s >>= 1) {
        if (tid < s) u_red[tid] = max(u_red[tid], u_red[tid + s]);
        __syncthreads();
    }
    const float mval = k2f(u_red[0]);

    unsigned int prefix = 0, prefmask = 0;
    int r = TOPK;
    for (int pass = 0; pass < 4; pass++) {
        const int shift = 24 - 8 * pass;
        hist[tid] = 0;
        __syncthreads();
        for (int i = tid; i < VOC; i += 256) {
            unsigned int k = keys[i];
            if ((k & prefmask) == prefix)
                atomicAdd(&hist[(k >> shift) & 255u], 1u);
        }
        __syncthreads();
        scanbuf[0][tid] = hist[tid];
        __syncthreads();
        int src = 0;
        for (int off = 1; off < 256; off <<= 1) {
            unsigned int val = scanbuf[src][tid];
            if (tid + off < 256) val += scanbuf[src][tid + off];
            scanbuf[src ^ 1][tid] = val;
            __syncthreads();
            src ^= 1;
        }
        const unsigned int cumb  = scanbuf[src][tid];
        const unsigned int cumb1 = (tid == 255) ? 0u : scanbuf[src][tid + 1];
        if (cumb >= (unsigned int)r && cumb1 < (unsigned int)r) {
            s_prefix = prefix | ((unsigned int)tid << shift);
            s_r = r - (int)cumb1;
        }
        __syncthreads();
        prefix = s_prefix;
        r = s_r;
        prefmask |= 0xFFu << shift;
        __syncthreads();
    }
    const unsigned int thresh = prefix;

    int c = 0;
    for (int i = tid; i < VOC; i += 256)
        if (keys[i] >= thresh) c++;
    scanbuf[0][tid] = (unsigned int)c;
    __syncthreads();
    int src = 0;
    for (int off = 1; off < 256; off <<= 1) {
        unsigned int val = scanbuf[src][tid];
        if (tid >= off) val += scanbuf[src][tid - off];
        scanbuf[src ^ 1][tid] = val;
        __syncthreads();
        src ^= 1;
    }
    int pos = (tid == 0) ? 0 : (int)scanbuf[src][tid - 1];
    const int total = (int)scanbuf[src][255];

    float lsum = 0.0f;
    for (int i = tid; i < VOC; i += 256) {
        unsigned int k = keys[i];
        if (k >= thresh) {
            float w = expf(k2f(k) - mval);
            if (pos < MAXSEL) { sel_idx[pos] = i; sel_w[pos] = w; }
            lsum += w;
            pos++;
        }
    }
    f_red[tid] = lsum;
    __syncthreads();
#pragma unroll
    for (int s = 128; s > 0; s >>= 1) {
        if (tid < s) f_red[tid] += f_red[tid + s];
        __syncthreads();
    }
    const float Z = f_red[0];
    const int count = min(total, MAXSEL);

    float acc0 = 0.0f, acc1 = 0.0f;
    const int d0 = tid * 2;
    for (int s = 0; s < count; s++) {
        const float w = sel_w[s];
        const float2 vv = *reinterpret_cast<const float2*>(
            v + (size_t)sel_idx[s] * DIM + d0);
        acc0 += w * vv.x;
        acc1 += w * vv.y;
    }
    const float inv = 1.0f / Z;
    float2 o;
    o.x = acc0 * inv;
    o.y = acc1 * inv;
    *reinterpret_cast<float2*>(out + (size_t)row * DIM + d0) = o;
}

// ---------------- launch ----------------------------------------------------
extern "C" void kernel_launch(void* const* d_in, const int* in_sizes, int n_in,
                              void* d_out, int out_size)
{
    const float* x  = (const float*)d_in[0];
    const float* cb = (const float*)d_in[1];
    const float* Wq = (const float*)d_in[2];
    const float* bq = (const float*)d_in[3];
    const float* Wk = (const float*)d_in[4];
    const float* bk = (const float*)d_in[5];
    const float* Wv = (const float*)d_in[6];
    const float* bv = (const float*)d_in[7];
    float* out = (float*)d_out;

    float *q, *k, *v, *qh, *ql, *kh, *kl, *dots;
    cudaGetSymbolAddress((void**)&q,    g_q);
    cudaGetSymbolAddress((void**)&k,    g_k);
    cudaGetSymbolAddress((void**)&v,    g_v);
    cudaGetSymbolAddress((void**)&qh,   g_qh);
    cudaGetSymbolAddress((void**)&ql,   g_ql);
    cudaGetSymbolAddress((void**)&kh,   g_kh);
    cudaGetSymbolAddress((void**)&kl,   g_kl);
    cudaGetSymbolAddress((void**)&dots, g_dots);

    cudaFuncSetAttribute(topk_softmax_gather,
                         cudaFuncAttributeMaxDynamicSharedMemorySize,
                         VOC * (int)sizeof(unsigned int));
    cudaFuncSetAttribute(dots_mma,
                         cudaFuncAttributeMaxDynamicSharedMemorySize,
                         2 * ST_BYTES);

    dim3 blk(256);

    // projections (fp32)
    sgemm128<false, true><<<dim3(DIM / 128, BATCH / 128), blk>>>(
        x, Wq, bq, q, BATCH, DIM, DIM);
    sgemm128<false, true><<<dim3(DIM / 128, VOC / 128), blk>>>(
        cb, Wk, bk, k, VOC, DIM, DIM);
    sgemm128<false, true><<<dim3(DIM / 128, VOC / 128), blk>>>(
        cb, Wv, bv, v, VOC, DIM, DIM);

    // tf32 splits of q and k
    split_tf32<<<(BATCH * DIM) / 256, blk>>>(q, qh, ql, BATCH * DIM);
    split_tf32<<<(VOC * DIM) / 256, blk>>>(k, kh, kl, VOC * DIM);

    // dots = q @ k^T via mma.sync 3xTF32
    dots_mma<<<dim3(BATCH / MT, VOC / NT), blk, 2 * ST_BYTES>>>(
        qh, ql, kh, kl, dots);

    // per-row top-64 threshold + softmax + sparse gather of v
    topk_softmax_gather<<<BATCH, blk, VOC * (int)sizeof(unsigned int)>>>(
        dots, v, out);
}